// round 1
// baseline (speedup 1.0000x reference)
#include <cuda_runtime.h>

// ---------------------------------------------------------------------------
// GTN forward, sparse-aware implementation.
// A: [4, 2048, 2048] with ~3 nnz/row per edge type (value 3.0).
// Strategy:
//   K1: softmax edge weights f1,f2 (with <1e-4 -> 0)
//   K2: sparsify A into per-row lists: col j, combined values
//       a1[c] = sum_e f1[c,e]*A[e,i,j], a2[c] likewise  (structure shared)
//   K3: XW = X @ Wg  (2048x512 @ 512x256 fp32 tiled GEMM)
//   K4: Y[c] = A2[c] @ XW  (sparse rows, gather XW rows)
//   K5: per row i: build sparse H row (scatter into 2x2048 smem accumulator),
//       threshold >0.05, degree + double-normalization coef, collect dropped
//       entries; out_row = relu(coef*(sum_s a1[s]*Y[k_s] - corrections) + bg)
// ---------------------------------------------------------------------------

#define NN 2048
#define NE 4
#define NC 2
#define WIN 512
#define WOUT 256
#define CAP 128              // max nnz per sparse row (Poisson(12) -> ample)
#define MAXDROP 256
#define THRESH 0.05f
#define WEPS 1e-4f

// Scratch (device globals; no allocations allowed)
__device__ float g_f1[NC][NE];
__device__ float g_f2[NC][NE];
__device__ int   g_nnz[NN];
__device__ int   g_cols[NN * CAP];
__device__ float g_a1[NN * CAP * NC];   // [row*CAP+slot]*2 + c
__device__ float g_a2[NN * CAP * NC];
__device__ float g_XW[NN * WOUT];
__device__ float g_Y[NC][NN * WOUT];

// ---------------------------------------------------------------- kernel 1
__global__ void k_weights(const float* __restrict__ W1a,
                          const float* __restrict__ W1b) {
    if (threadIdx.x == 0) {
        for (int c = 0; c < NC; c++) {
            // softmax over edge dim for W1a
            float m = -1e30f;
            for (int e = 0; e < NE; e++) m = fmaxf(m, W1a[c * NE + e]);
            float ex[NE], s = 0.f;
            for (int e = 0; e < NE; e++) { ex[e] = expf(W1a[c * NE + e] - m); s += ex[e]; }
            for (int e = 0; e < NE; e++) {
                float f = ex[e] / s;
                g_f1[c][e] = (f < WEPS) ? 0.f : f;
            }
            m = -1e30f;
            for (int e = 0; e < NE; e++) m = fmaxf(m, W1b[c * NE + e]);
            s = 0.f;
            for (int e = 0; e < NE; e++) { ex[e] = expf(W1b[c * NE + e] - m); s += ex[e]; }
            for (int e = 0; e < NE; e++) {
                float f = ex[e] / s;
                g_f2[c][e] = (f < WEPS) ? 0.f : f;
            }
        }
    }
}

// ---------------------------------------------------------------- kernel 2
// One block per row i; scan A[e][i][:] for all 4 edge types, emit sparse list.
__global__ void k_sparsify(const float* __restrict__ A) {
    const int i = blockIdx.x;
    __shared__ int cnt;
    __shared__ float f1s[NC][NE], f2s[NC][NE];
    if (threadIdx.x == 0) cnt = 0;
    if (threadIdx.x < NC * NE) {
        int c = threadIdx.x / NE, e = threadIdx.x % NE;
        f1s[c][e] = g_f1[c][e];
        f2s[c][e] = g_f2[c][e];
    }
    __syncthreads();

    const size_t planeStride = (size_t)NN * NN;
    const float* base = A + (size_t)i * NN;

    // 256 threads * 4 floats * 2 groups = 2048 columns
    for (int g = 0; g < 2; g++) {
        int j0 = threadIdx.x * 4 + g * 1024;
        float4 v[NE];
        #pragma unroll
        for (int e = 0; e < NE; e++)
            v[e] = *(const float4*)(base + (size_t)e * planeStride + j0);

        #pragma unroll
        for (int l = 0; l < 4; l++) {
            float a[NE];
            a[0] = l == 0 ? v[0].x : l == 1 ? v[0].y : l == 2 ? v[0].z : v[0].w;
            a[1] = l == 0 ? v[1].x : l == 1 ? v[1].y : l == 2 ? v[1].z : v[1].w;
            a[2] = l == 0 ? v[2].x : l == 1 ? v[2].y : l == 2 ? v[2].z : v[2].w;
            a[3] = l == 0 ? v[3].x : l == 1 ? v[3].y : l == 2 ? v[3].z : v[3].w;
            bool nz = (a[0] != 0.f) | (a[1] != 0.f) | (a[2] != 0.f) | (a[3] != 0.f);
            if (nz) {
                float v1[NC], v2[NC];
                #pragma unroll
                for (int c = 0; c < NC; c++) {
                    v1[c] = f1s[c][0] * a[0] + f1s[c][1] * a[1] +
                            f1s[c][2] * a[2] + f1s[c][3] * a[3];
                    v2[c] = f2s[c][0] * a[0] + f2s[c][1] * a[1] +
                            f2s[c][2] * a[2] + f2s[c][3] * a[3];
                }
                int slot = atomicAdd(&cnt, 1);
                if (slot < CAP) {
                    int idx = i * CAP + slot;
                    g_cols[idx] = j0 + l;
                    g_a1[idx * 2 + 0] = v1[0];
                    g_a1[idx * 2 + 1] = v1[1];
                    g_a2[idx * 2 + 0] = v2[0];
                    g_a2[idx * 2 + 1] = v2[1];
                }
            }
        }
    }
    __syncthreads();
    if (threadIdx.x == 0) g_nnz[i] = min(cnt, CAP);
}

// ---------------------------------------------------------------- kernel 3
// XW = X @ Wg : [2048,512] @ [512,256]. 64x64 tiles, 256 threads, 4x4/thread.
__global__ void k_gemm(const float* __restrict__ X, const float* __restrict__ Wg) {
    __shared__ float As[16][64];
    __shared__ float Bs[16][64];
    const int bm = blockIdx.y * 64;
    const int bn = blockIdx.x * 64;
    const int tx = threadIdx.x % 16;
    const int ty = threadIdx.x / 16;
    float acc[4][4] = {};

    for (int k0 = 0; k0 < WIN; k0 += 16) {
        #pragma unroll
        for (int t = 0; t < 4; t++) {
            int idx = threadIdx.x + t * 256;
            int m = idx / 16, k = idx % 16;
            As[k][m] = X[(size_t)(bm + m) * WIN + k0 + k];
        }
        #pragma unroll
        for (int t = 0; t < 4; t++) {
            int idx = threadIdx.x + t * 256;
            int kk = idx / 64, n = idx % 64;
            Bs[kk][n] = Wg[(size_t)(k0 + kk) * WOUT + bn + n];
        }
        __syncthreads();
        #pragma unroll
        for (int k = 0; k < 16; k++) {
            float a[4], b[4];
            #pragma unroll
            for (int u = 0; u < 4; u++) a[u] = As[k][ty * 4 + u];
            #pragma unroll
            for (int v = 0; v < 4; v++) b[v] = Bs[k][tx * 4 + v];
            #pragma unroll
            for (int u = 0; u < 4; u++)
                #pragma unroll
                for (int v = 0; v < 4; v++)
                    acc[u][v] = fmaf(a[u], b[v], acc[u][v]);
        }
        __syncthreads();
    }
    #pragma unroll
    for (int u = 0; u < 4; u++)
        #pragma unroll
        for (int v = 0; v < 4; v++)
            g_XW[(size_t)(bm + ty * 4 + u) * WOUT + bn + tx * 4 + v] = acc[u][v];
}

// ---------------------------------------------------------------- kernel 4
// Y[c][k][:] = sum_s a2[c][k][s] * XW[col[s]][:]
__global__ void k_y() {
    const int k = blockIdx.x;
    const int f = threadIdx.x;   // 256 threads
    __shared__ int   scol[CAP];
    __shared__ float sv[CAP][2];
    __shared__ int nsh;
    if (threadIdx.x == 0) nsh = g_nnz[k];
    __syncthreads();
    const int n2 = nsh;
    for (int s = threadIdx.x; s < n2; s += 256) {
        int idx = k * CAP + s;
        scol[s] = g_cols[idx];
        sv[s][0] = g_a2[idx * 2 + 0];
        sv[s][1] = g_a2[idx * 2 + 1];
    }
    __syncthreads();
    float acc0 = 0.f, acc1 = 0.f;
    for (int s = 0; s < n2; s++) {
        float x = g_XW[(size_t)scol[s] * WOUT + f];
        acc0 = fmaf(sv[s][0], x, acc0);
        acc1 = fmaf(sv[s][1], x, acc1);
    }
    g_Y[0][(size_t)k * WOUT + f] = acc0;
    g_Y[1][(size_t)k * WOUT + f] = acc1;
}

// ---------------------------------------------------------------- kernel 5
__global__ void k_final(const float* __restrict__ bg, float* __restrict__ out) {
    const int i = blockIdx.x;
    const int tid = threadIdx.x;   // 256

    __shared__ float H[NC][NN];           // 16 KB dense row accumulators
    __shared__ int   c1[CAP];
    __shared__ float v1s[CAP][2];
    __shared__ int   nn1;
    __shared__ float degsh[NC];
    __shared__ int   dropn[NC];
    __shared__ int   dropj[NC][MAXDROP];
    __shared__ float droph[NC][MAXDROP];

    for (int t = tid; t < NN; t += 256) { H[0][t] = 0.f; H[1][t] = 0.f; }
    if (tid == 0) {
        nn1 = g_nnz[i];
        degsh[0] = degsh[1] = 0.f;
        dropn[0] = dropn[1] = 0;
    }
    __syncthreads();
    const int n1 = nn1;

    for (int s = tid; s < n1; s += 256) {
        int idx = i * CAP + s;
        c1[s] = g_cols[idx];
        v1s[s][0] = g_a1[idx * 2 + 0];
        v1s[s][1] = g_a1[idx * 2 + 1];
    }
    __syncthreads();

    // scatter H row contributions
    for (int s = tid; s < n1; s += 256) {
        int k = c1[s];
        int n2 = g_nnz[k];
        float w0 = v1s[s][0], w1 = v1s[s][1];
        for (int s2 = 0; s2 < n2; s2++) {
            int idx = k * CAP + s2;
            int j = g_cols[idx];
            float h0 = w0 * g_a2[idx * 2 + 0];
            float h1 = w1 * g_a2[idx * 2 + 1];
            if (h0 != 0.f) atomicAdd(&H[0][j], h0);
            if (h1 != 0.f) atomicAdd(&H[1][j], h1);
        }
    }
    __syncthreads();

    // threshold scan: degree sums + dropped-entry lists
    float d0 = 0.f, d1 = 0.f;
    for (int j = tid; j < NN; j += 256) {
        float h0 = H[0][j];
        if (h0 > THRESH) d0 += h0;
        else if (h0 > 0.f) {
            int p = atomicAdd(&dropn[0], 1);
            if (p < MAXDROP) { dropj[0][p] = j; droph[0][p] = h0; }
        }
        float h1 = H[1][j];
        if (h1 > THRESH) d1 += h1;
        else if (h1 > 0.f) {
            int p = atomicAdd(&dropn[1], 1);
            if (p < MAXDROP) { dropj[1][p] = j; droph[1][p] = h1; }
        }
    }
    if (d0 != 0.f) atomicAdd(&degsh[0], d0);
    if (d1 != 0.f) atomicAdd(&degsh[1], d1);
    __syncthreads();

    float coef[NC];
    #pragma unroll
    for (int c = 0; c < NC; c++) {
        float deg = degsh[c];
        if (deg > 0.f) {
            float dinv = 1.f / deg;
            float deg2 = deg * dinv;        // ~= 1 (double-normalization)
            coef[c] = dinv * (1.f / deg2);
        } else {
            coef[c] = 0.f;
        }
    }

    // output: feature f = tid
    const int f = tid;
    const float bias = bg[f];
    #pragma unroll
    for (int c = 0; c < NC; c++) {
        float acc = 0.f;
        for (int s = 0; s < n1; s++)
            acc = fmaf(v1s[s][c], g_Y[c][(size_t)c1[s] * WOUT + f], acc);
        int nd = min(dropn[c], MAXDROP);
        for (int d = 0; d < nd; d++)
            acc -= droph[c][d] * g_XW[(size_t)dropj[c][d] * WOUT + f];
        float o = coef[c] * acc + bias;
        out[(size_t)i * (NC * WOUT) + c * WOUT + f] = fmaxf(o, 0.f);
    }
}

// ---------------------------------------------------------------------------
extern "C" void kernel_launch(void* const* d_in, const int* in_sizes, int n_in,
                              void* d_out, int out_size) {
    const float* A   = (const float*)d_in[0];
    const float* X   = (const float*)d_in[1];
    const float* W1a = (const float*)d_in[2];
    const float* W1b = (const float*)d_in[3];
    const float* Wg  = (const float*)d_in[4];
    const float* bg  = (const float*)d_in[5];
    float* out = (float*)d_out;

    k_weights<<<1, 32>>>(W1a, W1b);
    k_sparsify<<<NN, 256>>>(A);
    dim3 gg(WOUT / 64, NN / 64);
    k_gemm<<<gg, 256>>>(X, Wg);
    k_y<<<NN, 256>>>();
    k_final<<<NN, 256>>>(bg, out);
}